// round 1
// baseline (speedup 1.0000x reference)
#include <cuda_runtime.h>
#include <math.h>

#define N_RES   500
#define N_SYSS  4
#define P_PAIRS 123256
#define NUM_W   52
#define BATCHN  256

// scratch (device globals; no allocations allowed)
__device__ __align__(16) float    g_w[N_RES * 4];
__device__ __align__(16) float    g_alpha[P_PAIRS * 4];
__device__             unsigned   g_maxbits[4];
__device__ __align__(16) float    g_invmax[4];

// ---------------- kernel 1: weights -> per-residue mixing weights ----------------
__global__ void k_weights(const float* __restrict__ weights) {
    __shared__ float ps[N_SYSS][NUM_W];
    int t = threadIdx.x;
    if (t < N_SYSS) {
        const float* row = weights + t * NUM_W;
        float m = row[0];
        for (int i = 1; i < NUM_W; i++) m = fmaxf(m, row[i]);
        float s = 0.0f;
        for (int i = 0; i < NUM_W; i++) s += expf(row[i] - m);
        float inv = 1.0f / s;
        for (int i = 0; i < NUM_W; i++) ps[t][i] = (expf(row[i] - m) * inv) * 52.0f;
    }
    if (t == N_SYSS) {
        g_maxbits[0] = 0u; g_maxbits[1] = 0u; g_maxbits[2] = 0u; g_maxbits[3] = 0u;
    }
    __syncthreads();
    for (int r = t; r < N_RES; r += blockDim.x) {
        int b0 = r / 10;              // SKIP=10, BALANCE=0, NB_PER_RES=3
        float v[N_SYSS];
        float sum = 0.0f;
        #pragma unroll
        for (int n = 0; n < N_SYSS; n++) {
            float prod = (ps[n][b0] * ps[n][b0 + 1]) * ps[n][b0 + 2];
            v[n] = fmaxf(prod - 0.5f, 0.0f);      // relu(w - CUTOFF)
            sum += v[n];
        }
        sum += 2.5f;                  // relu(FACTOR_FAKE - CUTOFF)
        #pragma unroll
        for (int n = 0; n < N_SYSS; n++) g_w[r * 4 + n] = v[n] / sum;
    }
}

// ---------------- kernel 2: alpha table + max reduction ----------------
__device__ __forceinline__ int tri_start(int i) {   // s(i) = 496*i - i*(i-1)/2
    return 496 * i - (i * (i - 1)) / 2;
}

__global__ void k_alpha() {
    int p = blockIdx.x * blockDim.x + threadIdx.x;
    float lm0 = 0.f, lm1 = 0.f, lm2 = 0.f, lm3 = 0.f;
    if (p < P_PAIRS) {
        int disc = 986049 - 8 * p;                 // 993^2 - 8p
        int i = (int)((993.0 - sqrt((double)disc)) * 0.5);
        if (i < 0) i = 0;
        while (i + 1 <= 495 && tri_start(i + 1) <= p) i++;
        while (i > 0 && tri_start(i) > p) i--;
        int j = p - tri_start(i) + i + 4;          // SKIP_RES=4
        float4 w1 = *(const float4*)(g_w + i * 4);
        float4 w2 = *(const float4*)(g_w + j * 4);
        float4 a;
        a.x = (w1.x * 5.0f) * (w2.x * 5.0f);
        a.y = (w1.y * 5.0f) * (w2.y * 5.0f);
        a.z = (w1.z * 5.0f) * (w2.z * 5.0f);
        a.w = (w1.w * 5.0f) * (w2.w * 5.0f);
        ((float4*)g_alpha)[p] = a;
        lm0 = a.x; lm1 = a.y; lm2 = a.z; lm3 = a.w;
    }
    #pragma unroll
    for (int off = 16; off > 0; off >>= 1) {
        lm0 = fmaxf(lm0, __shfl_xor_sync(0xffffffffu, lm0, off));
        lm1 = fmaxf(lm1, __shfl_xor_sync(0xffffffffu, lm1, off));
        lm2 = fmaxf(lm2, __shfl_xor_sync(0xffffffffu, lm2, off));
        lm3 = fmaxf(lm3, __shfl_xor_sync(0xffffffffu, lm3, off));
    }
    if ((threadIdx.x & 31) == 0) {
        atomicMax(&g_maxbits[0], __float_as_uint(lm0));   // all values >= 0
        atomicMax(&g_maxbits[1], __float_as_uint(lm1));
        atomicMax(&g_maxbits[2], __float_as_uint(lm2));
        atomicMax(&g_maxbits[3], __float_as_uint(lm3));
    }
}

// ---------------- kernel 3: reciprocals of max ----------------
__global__ void k_invmax() {
    int t = threadIdx.x;
    if (t < 4) g_invmax[t] = 1.0f / __uint_as_float(g_maxbits[t]);
}

// ---------------- threefry2x32 for key (0, 42), partitionable counter (0, c) ----------------
__device__ __forceinline__ void tf_round(unsigned& x0, unsigned& x1, int r) {
    x0 += x1;
    x1 = __funnelshift_l(x1, x1, r) ^ x0;
}

__device__ __forceinline__ unsigned threefry_bits(unsigned c) {
    const unsigned ks1 = 42u;
    const unsigned ks2 = 0x1BD11BDAu ^ 42u;        // ks0 = 0
    unsigned x0 = 0u;                              // count_hi + ks0
    unsigned x1 = c + ks1;                         // count_lo + ks1
    tf_round(x0, x1, 13); tf_round(x0, x1, 15); tf_round(x0, x1, 26); tf_round(x0, x1, 6);
    x0 += ks1; x1 += ks2 + 1u;
    tf_round(x0, x1, 17); tf_round(x0, x1, 29); tf_round(x0, x1, 16); tf_round(x0, x1, 24);
    x0 += ks2; x1 += 2u;                           // + ks0 + 2
    tf_round(x0, x1, 13); tf_round(x0, x1, 15); tf_round(x0, x1, 26); tf_round(x0, x1, 6);
    /* x0 += ks0 */ x1 += ks1 + 3u;
    tf_round(x0, x1, 17); tf_round(x0, x1, 29); tf_round(x0, x1, 16); tf_round(x0, x1, 24);
    x0 += ks1; x1 += ks2 + 4u;
    tf_round(x0, x1, 13); tf_round(x0, x1, 15); tf_round(x0, x1, 26); tf_round(x0, x1, 6);
    x0 += ks2; x1 += 5u;                           // + ks0 + 5
    return x0 ^ x1;                                // 32-bit partitionable fold
}

// bits -> N(0,1) exactly as jax.random.normal (f32)
__device__ __forceinline__ float bits_to_normal(unsigned bits) {
    float f = __uint_as_float(0x3f800000u | (bits >> 9)) - 1.0f;   // [0, 1)
    float u = fmaf(f, 2.0f, -0.99999994f);                         // lo=nextafter(-1,0), hi-lo==2.0f
    return 1.4142135623730951f * erfinvf(u);
}

// ---------------- kernel 4: main fused output ----------------
__global__ void __launch_bounds__(256) k_main(
    const float* __restrict__ x,
    const float* __restrict__ mean,
    const float* __restrict__ stdv,
    float4* __restrict__ out)
{
    unsigned tid = blockIdx.x * 256u + threadIdx.x;   // tid = b*P + p, fully coalesced
    unsigned p = tid % (unsigned)P_PAIRS;

    float xv = x[tid];
    float mu = __ldg(mean + p);
    float sd = __ldg(stdv + p);
    float xn = (xv - mu) / sd;

    float4 a  = __ldg((const float4*)g_alpha + p);
    float4 iv = *(const float4*)g_invmax;

    float q0 = 1.0f - a.x * iv.x;
    float q1 = 1.0f - a.y * iv.y;
    float q2 = 1.0f - a.z * iv.z;
    float q3 = 1.0f - a.w * iv.w;

    unsigned base = tid * 4u;
    float n0 = bits_to_normal(threefry_bits(base + 0u));
    float n1 = bits_to_normal(threefry_bits(base + 1u));
    float n2 = bits_to_normal(threefry_bits(base + 2u));
    float n3 = bits_to_normal(threefry_bits(base + 3u));

    float4 o;
    o.x = fmaf(xn, a.x, q0 * (0.5f * n0));   // NOISE = 0.5
    o.y = fmaf(xn, a.y, q1 * (0.5f * n1));
    o.z = fmaf(xn, a.z, q2 * (0.5f * n2));
    o.w = fmaf(xn, a.w, q3 * (0.5f * n3));
    out[tid] = o;
}

// ---------------- launch ----------------
extern "C" void kernel_launch(void* const* d_in, const int* in_sizes, int n_in,
                              void* d_out, int out_size)
{
    const float* x       = (const float*)d_in[0];
    const float* mean    = (const float*)d_in[1];
    const float* stdv    = (const float*)d_in[2];
    const float* weights = (const float*)d_in[3];

    k_weights<<<1, 128>>>(weights);
    k_alpha<<<(P_PAIRS + 255) / 256, 256>>>();
    k_invmax<<<1, 32>>>();
    // BATCH * P_PAIRS threads, one float4 (4 outputs) each: grid = 256*123256/256
    k_main<<<(BATCHN * P_PAIRS) / 256, 256>>>(x, mean, stdv, (float4*)d_out);
    (void)in_sizes; (void)n_in; (void)out_size;
}

// round 2
// speedup vs baseline: 1.0108x; 1.0108x over previous
#include <cuda_runtime.h>
#include <math.h>

#define N_RES   500
#define N_SYSS  4
#define P_PAIRS 123256
#define NUM_W   52
#define BATCHN  256

// scratch (device globals; no allocations allowed)
__device__ __align__(16) float    g_w[N_RES * 4];
__device__ __align__(16) float    g_alpha[P_PAIRS * 4];
__device__             unsigned   g_maxbits[4];
__device__ __align__(16) float    g_invmax[4];

// ---------------- kernel 1: weights -> per-residue mixing weights ----------------
__global__ void k_weights(const float* __restrict__ weights) {
    __shared__ float ps[N_SYSS][NUM_W];
    int t = threadIdx.x;
    if (t < N_SYSS) {
        const float* row = weights + t * NUM_W;
        float m = row[0];
        for (int i = 1; i < NUM_W; i++) m = fmaxf(m, row[i]);
        float s = 0.0f;
        for (int i = 0; i < NUM_W; i++) s += expf(row[i] - m);
        float inv = 1.0f / s;
        for (int i = 0; i < NUM_W; i++) ps[t][i] = (expf(row[i] - m) * inv) * 52.0f;
    }
    if (t == N_SYSS) {
        g_maxbits[0] = 0u; g_maxbits[1] = 0u; g_maxbits[2] = 0u; g_maxbits[3] = 0u;
    }
    __syncthreads();
    for (int r = t; r < N_RES; r += blockDim.x) {
        int b0 = r / 10;              // SKIP=10, BALANCE=0, NB_PER_RES=3
        float v[N_SYSS];
        float sum = 0.0f;
        #pragma unroll
        for (int n = 0; n < N_SYSS; n++) {
            float prod = (ps[n][b0] * ps[n][b0 + 1]) * ps[n][b0 + 2];
            v[n] = fmaxf(prod - 0.5f, 0.0f);      // relu(w - CUTOFF)
            sum += v[n];
        }
        sum += 2.5f;                  // relu(FACTOR_FAKE - CUTOFF)
        #pragma unroll
        for (int n = 0; n < N_SYSS; n++) g_w[r * 4 + n] = v[n] / sum;
    }
}

// ---------------- kernel 2: alpha table + max reduction ----------------
__device__ __forceinline__ int tri_start(int i) {   // s(i) = 496*i - i*(i-1)/2
    return 496 * i - (i * (i - 1)) / 2;
}

__global__ void k_alpha() {
    int p = blockIdx.x * blockDim.x + threadIdx.x;
    float lm0 = 0.f, lm1 = 0.f, lm2 = 0.f, lm3 = 0.f;
    if (p < P_PAIRS) {
        int disc = 986049 - 8 * p;                 // 993^2 - 8p
        int i = (int)((993.0 - sqrt((double)disc)) * 0.5);
        if (i < 0) i = 0;
        while (i + 1 <= 495 && tri_start(i + 1) <= p) i++;
        while (i > 0 && tri_start(i) > p) i--;
        int j = p - tri_start(i) + i + 4;          // SKIP_RES=4
        float4 w1 = *(const float4*)(g_w + i * 4);
        float4 w2 = *(const float4*)(g_w + j * 4);
        float4 a;
        a.x = (w1.x * 5.0f) * (w2.x * 5.0f);
        a.y = (w1.y * 5.0f) * (w2.y * 5.0f);
        a.z = (w1.z * 5.0f) * (w2.z * 5.0f);
        a.w = (w1.w * 5.0f) * (w2.w * 5.0f);
        ((float4*)g_alpha)[p] = a;
        lm0 = a.x; lm1 = a.y; lm2 = a.z; lm3 = a.w;
    }
    #pragma unroll
    for (int off = 16; off > 0; off >>= 1) {
        lm0 = fmaxf(lm0, __shfl_xor_sync(0xffffffffu, lm0, off));
        lm1 = fmaxf(lm1, __shfl_xor_sync(0xffffffffu, lm1, off));
        lm2 = fmaxf(lm2, __shfl_xor_sync(0xffffffffu, lm2, off));
        lm3 = fmaxf(lm3, __shfl_xor_sync(0xffffffffu, lm3, off));
    }
    if ((threadIdx.x & 31) == 0) {
        atomicMax(&g_maxbits[0], __float_as_uint(lm0));   // all values >= 0
        atomicMax(&g_maxbits[1], __float_as_uint(lm1));
        atomicMax(&g_maxbits[2], __float_as_uint(lm2));
        atomicMax(&g_maxbits[3], __float_as_uint(lm3));
    }
}

// ---------------- kernel 3: reciprocals of max ----------------
__global__ void k_invmax() {
    int t = threadIdx.x;
    if (t < 4) g_invmax[t] = 1.0f / __uint_as_float(g_maxbits[t]);
}

// ---------------- forced-IMAD helpers (fma pipe; `one` is an opaque runtime 1) ----------------
__device__ __forceinline__ unsigned madd_r(unsigned a, unsigned one, unsigned b) {
    unsigned r;
    asm("mad.lo.u32 %0, %1, %2, %3;" : "=r"(r) : "r"(a), "r"(one), "r"(b));
    return r;   // a*one + b
}
template <unsigned K>
__device__ __forceinline__ unsigned madd_k(unsigned one, unsigned b) {
    unsigned r;
    asm("mad.lo.u32 %0, %1, %2, %3;" : "=r"(r) : "r"(one), "n"(K), "r"(b));
    return r;   // one*K + b
}
__device__ __forceinline__ unsigned rotxor(unsigned x1, int r, unsigned x0) {
    return __funnelshift_l(x1, x1, r) ^ x0;     // SHF + LOP3 (alu)
}

// ---------------- threefry2x32, key (0,42), counter (0,c), partitionable fold ----------------
__device__ __forceinline__ unsigned threefry_bits(unsigned c, unsigned one) {
    // ks0 = 0, ks1 = 42, ks2 = 0x1BD11BDA ^ 42 = 0x1BD11BF0
    unsigned x1 = c + 42u;
    unsigned x0 = x1;                                   // round-1 add folded (x0 was 0)
    x1 = rotxor(x1, 13, x0);
    x0 = madd_r(x1, one, x0); x1 = rotxor(x1, 15, x0);
    x0 = madd_r(x1, one, x0); x1 = rotxor(x1, 26, x0);
    x0 = madd_r(x1, one, x0); x1 = rotxor(x1,  6, x0);
    x0 = madd_k<42u>(one, x0);          x1 = madd_k<0x1BD11BF1u>(one, x1);   // ks1 ; ks2+1
    x0 = madd_r(x1, one, x0); x1 = rotxor(x1, 17, x0);
    x0 = madd_r(x1, one, x0); x1 = rotxor(x1, 29, x0);
    x0 = madd_r(x1, one, x0); x1 = rotxor(x1, 16, x0);
    x0 = madd_r(x1, one, x0); x1 = rotxor(x1, 24, x0);
    x0 = madd_k<0x1BD11BF0u>(one, x0);  x1 = madd_k<2u>(one, x1);            // ks2 ; ks0+2
    x0 = madd_r(x1, one, x0); x1 = rotxor(x1, 13, x0);
    x0 = madd_r(x1, one, x0); x1 = rotxor(x1, 15, x0);
    x0 = madd_r(x1, one, x0); x1 = rotxor(x1, 26, x0);
    x0 = madd_r(x1, one, x0); x1 = rotxor(x1,  6, x0);
    /* x0 += ks0 (0) */                 x1 = madd_k<45u>(one, x1);           // ks1+3
    x0 = madd_r(x1, one, x0); x1 = rotxor(x1, 17, x0);
    x0 = madd_r(x1, one, x0); x1 = rotxor(x1, 29, x0);
    x0 = madd_r(x1, one, x0); x1 = rotxor(x1, 16, x0);
    x0 = madd_r(x1, one, x0); x1 = rotxor(x1, 24, x0);
    x0 = madd_k<42u>(one, x0);          x1 = madd_k<0x1BD11BF4u>(one, x1);   // ks1 ; ks2+4
    x0 = madd_r(x1, one, x0); x1 = rotxor(x1, 13, x0);
    x0 = madd_r(x1, one, x0); x1 = rotxor(x1, 15, x0);
    x0 = madd_r(x1, one, x0); x1 = rotxor(x1, 26, x0);
    x0 = madd_r(x1, one, x0); x1 = rotxor(x1,  6, x0);
    x0 = madd_k<0x1BD11BF0u>(one, x0);  x1 = madd_k<5u>(one, x1);            // ks2 ; ks0+5
    return x0 ^ x1;                                     // 32-bit partitionable fold
}

// ---------------- bits -> 0.5 * N(0,1)  (Giles erfinv, coeffs pre-scaled by sqrt(2)/2) ----------------
__device__ __forceinline__ float noise_half(unsigned bits) {
    float g = __uint_as_float(0x3f800000u | (bits >> 9));
    float f = g - 1.0f;                               // exact, matches JAX
    float u = fmaf(f, 2.0f, -0.99999994f);            // uniform in (-1, 1)
    float t = fmaf(-u, u, 1.0f);                      // 1 - u^2  (> 0)
    float w = __log2f(t) * -0.693147180559945f;       // -ln(1-u^2)
    float p;
    if (w < 5.0f) {
        float s = w - 2.5f;
        p =             1.987138e-08f;
        p = fmaf(p, s,  2.427323e-07f);
        p = fmaf(p, s, -2.491411e-06f);
        p = fmaf(p, s, -3.105282e-06f);
        p = fmaf(p, s,  1.545603e-04f);
        p = fmaf(p, s, -8.865218e-04f);
        p = fmaf(p, s, -2.954063e-03f);
        p = fmaf(p, s,  1.7440262e-01f);
        p = fmaf(p, s,  1.0616583f);
    } else {
        float s = sqrtf(w) - 3.0f;
        p =            -1.415729e-04f;
        p = fmaf(p, s,  7.138285e-05f);
        p = fmaf(p, s,  9.541345e-04f);
        p = fmaf(p, s, -2.597603e-03f);
        p = fmaf(p, s,  4.058407e-03f);
        p = fmaf(p, s, -5.389894e-03f);
        p = fmaf(p, s,  6.674289e-03f);
        p = fmaf(p, s,  7.082905e-01f);
        p = fmaf(p, s,  2.0032171f);
    }
    return u * p;        // = 0.5 * sqrt(2) * erfinv(u) = 0.5 * normal
}

// ---------------- kernel 4: main fused output ----------------
__global__ void __launch_bounds__(256) k_main(
    const float* __restrict__ x,
    const float* __restrict__ mean,
    const float* __restrict__ stdv,
    float4* __restrict__ out,
    unsigned one)
{
    unsigned tid = blockIdx.x * 256u + threadIdx.x;   // tid = b*P + p, fully coalesced
    unsigned p = tid % (unsigned)P_PAIRS;

    float xv = x[tid];
    float mu = __ldg(mean + p);
    float sd = __ldg(stdv + p);
    float xn = __fdividef(xv - mu, sd);

    float4 a  = __ldg((const float4*)g_alpha + p);
    float4 iv = *(const float4*)g_invmax;

    unsigned base = tid * 4u;
    float h0 = noise_half(threefry_bits(base + 0u, one));
    float h1 = noise_half(threefry_bits(base + 1u, one));
    float h2 = noise_half(threefry_bits(base + 2u, one));
    float h3 = noise_half(threefry_bits(base + 3u, one));

    float4 o;
    o.x = fmaf(xn, a.x, (1.0f - a.x * iv.x) * h0);
    o.y = fmaf(xn, a.y, (1.0f - a.y * iv.y) * h1);
    o.z = fmaf(xn, a.z, (1.0f - a.z * iv.z) * h2);
    o.w = fmaf(xn, a.w, (1.0f - a.w * iv.w) * h3);
    out[tid] = o;
}

// ---------------- launch ----------------
extern "C" void kernel_launch(void* const* d_in, const int* in_sizes, int n_in,
                              void* d_out, int out_size)
{
    const float* x       = (const float*)d_in[0];
    const float* mean    = (const float*)d_in[1];
    const float* stdv    = (const float*)d_in[2];
    const float* weights = (const float*)d_in[3];

    k_weights<<<1, 128>>>(weights);
    k_alpha<<<(P_PAIRS + 255) / 256, 256>>>();
    k_invmax<<<1, 32>>>();
    k_main<<<(BATCHN * P_PAIRS) / 256, 256>>>(x, mean, stdv, (float4*)d_out, 1u);
    (void)in_sizes; (void)n_in; (void)out_size;
}

// round 3
// speedup vs baseline: 1.1371x; 1.1250x over previous
#include <cuda_runtime.h>
#include <math.h>

#define N_RES   500
#define N_SYSS  4
#define P_PAIRS 123256
#define NUM_W   52
#define BATCHN  256

typedef unsigned long long ull;

// scratch (device globals; no allocations allowed)
__device__ __align__(16) float g_alpha[P_PAIRS * 4];
__device__ __align__(16) float g_negiv[4];     // -1/max_alpha per subsystem

// ================= packed f32x2 helpers =================
__device__ __forceinline__ ull pk2(float a, float b) {
    ull r; asm("mov.b64 %0, {%1, %2};" : "=l"(r) : "f"(a), "f"(b)); return r;
}
__device__ __forceinline__ void upk2(float& a, float& b, ull v) {
    asm("mov.b64 {%0, %1}, %2;" : "=f"(a), "=f"(b) : "l"(v));
}
__device__ __forceinline__ ull fma2(ull a, ull b, ull c) {
    ull d; asm("fma.rn.f32x2 %0, %1, %2, %3;" : "=l"(d) : "l"(a), "l"(b), "l"(c)); return d;
}
__device__ __forceinline__ ull mul2(ull a, ull b) {
    ull d; asm("mul.rn.f32x2 %0, %1, %2;" : "=l"(d) : "l"(a), "l"(b)); return d;
}
__device__ __forceinline__ ull add2(ull a, ull b) {
    ull d; asm("add.rn.f32x2 %0, %1, %2;" : "=l"(d) : "l"(a), "l"(b)); return d;
}

// ================= setup kernel (weights -> alpha table + -1/max) =================
__global__ void k_setup(const float* __restrict__ weights) {
    __shared__ float ps[N_SYSS][NUM_W];
    __shared__ float w[N_RES][N_SYSS];
    int t = threadIdx.x;
    if (t < N_SYSS) {
        const float* row = weights + t * NUM_W;
        float m = row[0];
        for (int i = 1; i < NUM_W; i++) m = fmaxf(m, row[i]);
        float s = 0.0f;
        for (int i = 0; i < NUM_W; i++) s += expf(row[i] - m);
        float inv = 1.0f / s;
        for (int i = 0; i < NUM_W; i++) ps[t][i] = (expf(row[i] - m) * inv) * 52.0f;
    }
    __syncthreads();
    for (int r = t; r < N_RES; r += 256) {
        int b0 = r / 10;                       // SKIP=10, BALANCE=0
        float v[N_SYSS]; float sum = 2.5f;     // relu(FACTOR_FAKE - CUTOFF)
        #pragma unroll
        for (int n = 0; n < N_SYSS; n++) {
            float prod = (ps[n][b0] * ps[n][b0 + 1]) * ps[n][b0 + 2];
            v[n] = fmaxf(prod - 0.5f, 0.0f);
            sum += v[n];
        }
        #pragma unroll
        for (int n = 0; n < N_SYSS; n++) w[r][n] = v[n] / sum;
    }
    __syncthreads();

    // block 0: analytic column max of alpha via gap-4 prefix-max scan
    if (blockIdx.x == 0 && t < N_SYSS) {
        float pm = w[0][t];
        float best = 0.0f;
        for (int j = 4; j < N_RES; j++) {
            pm = fmaxf(pm, w[j - 4][t]);
            best = fmaxf(best, (pm * 5.0f) * (w[j][t] * 5.0f));
        }
        g_negiv[t] = -1.0f / best;
    }

    // alpha table slice for this block
    int p = blockIdx.x * 256 + t;
    if (p < P_PAIRS) {
        int i = (int)((993.0 - sqrt((double)(986049 - 8 * p))) * 0.5);
        if (i < 0) i = 0;
        // tri_start(i) = 496*i - i*(i-1)/2
        while (i + 1 <= 495 && (496 * (i + 1) - ((i + 1) * i) / 2) <= p) i++;
        while (i > 0 && (496 * i - (i * (i - 1)) / 2) > p) i--;
        int j = p - (496 * i - (i * (i - 1)) / 2) + i + 4;
        float4 a;
        a.x = (w[i][0] * 5.0f) * (w[j][0] * 5.0f);
        a.y = (w[i][1] * 5.0f) * (w[j][1] * 5.0f);
        a.z = (w[i][2] * 5.0f) * (w[j][2] * 5.0f);
        a.w = (w[i][3] * 5.0f) * (w[j][3] * 5.0f);
        ((float4*)g_alpha)[p] = a;
    }
}

// ================= forced-IMAD helpers (`one` = opaque runtime 1) =================
__device__ __forceinline__ unsigned madd_r(unsigned a, unsigned one, unsigned b) {
    unsigned r; asm("mad.lo.u32 %0, %1, %2, %3;" : "=r"(r) : "r"(a), "r"(one), "r"(b)); return r;
}
template <unsigned K>
__device__ __forceinline__ unsigned madd_k(unsigned one, unsigned b) {
    unsigned r; asm("mad.lo.u32 %0, %1, %2, %3;" : "=r"(r) : "r"(one), "n"(K), "r"(b)); return r;
}
__device__ __forceinline__ unsigned rotxor(unsigned x1, int r, unsigned x0) {
    return __funnelshift_l(x1, x1, r) ^ x0;     // SHF + LOP3 (alu)
}

// threefry2x32, key (0,42), counter (0,c), partitionable fold (verified bit-exact R1/R2)
__device__ __forceinline__ unsigned threefry_bits(unsigned c, unsigned one) {
    unsigned x1 = c + 42u;
    unsigned x0 = x1;                                   // round-1 add folded (x0 was 0)
    x1 = rotxor(x1, 13, x0);
    x0 = madd_r(x1, one, x0); x1 = rotxor(x1, 15, x0);
    x0 = madd_r(x1, one, x0); x1 = rotxor(x1, 26, x0);
    x0 = madd_r(x1, one, x0); x1 = rotxor(x1,  6, x0);
    x0 = madd_k<42u>(one, x0);          x1 = madd_k<0x1BD11BF1u>(one, x1);
    x0 = madd_r(x1, one, x0); x1 = rotxor(x1, 17, x0);
    x0 = madd_r(x1, one, x0); x1 = rotxor(x1, 29, x0);
    x0 = madd_r(x1, one, x0); x1 = rotxor(x1, 16, x0);
    x0 = madd_r(x1, one, x0); x1 = rotxor(x1, 24, x0);
    x0 = madd_k<0x1BD11BF0u>(one, x0);  x1 = madd_k<2u>(one, x1);
    x0 = madd_r(x1, one, x0); x1 = rotxor(x1, 13, x0);
    x0 = madd_r(x1, one, x0); x1 = rotxor(x1, 15, x0);
    x0 = madd_r(x1, one, x0); x1 = rotxor(x1, 26, x0);
    x0 = madd_r(x1, one, x0); x1 = rotxor(x1,  6, x0);
                                        x1 = madd_k<45u>(one, x1);
    x0 = madd_r(x1, one, x0); x1 = rotxor(x1, 17, x0);
    x0 = madd_r(x1, one, x0); x1 = rotxor(x1, 29, x0);
    x0 = madd_r(x1, one, x0); x1 = rotxor(x1, 16, x0);
    x0 = madd_r(x1, one, x0); x1 = rotxor(x1, 24, x0);
    x0 = madd_k<42u>(one, x0);          x1 = madd_k<0x1BD11BF4u>(one, x1);
    x0 = madd_r(x1, one, x0); x1 = rotxor(x1, 13, x0);
    x0 = madd_r(x1, one, x0); x1 = rotxor(x1, 15, x0);
    x0 = madd_r(x1, one, x0); x1 = rotxor(x1, 26, x0);
    x0 = madd_r(x1, one, x0); x1 = rotxor(x1,  6, x0);
    x0 = madd_k<0x1BD11BF0u>(one, x0);  x1 = madd_k<5u>(one, x1);
    return x0 ^ x1;
}

// rare tail of Giles erfinv (w >= 5), coeffs pre-scaled by sqrt(2)/2
__device__ __noinline__ float tail_fix(float u, float l) {
    float w = l * -0.693147180559945f;
    float s = sqrtf(w) - 3.0f;
    float p =          -1.415729e-04f;
    p = fmaf(p, s,  7.138285e-05f);
    p = fmaf(p, s,  9.541345e-04f);
    p = fmaf(p, s, -2.597603e-03f);
    p = fmaf(p, s,  4.058407e-03f);
    p = fmaf(p, s, -5.389894e-03f);
    p = fmaf(p, s,  6.674289e-03f);
    p = fmaf(p, s,  7.082905e-01f);
    p = fmaf(p, s,  2.0032171f);
    return u * p;
}

#define LCUT (-7.21347520444482f)   // l <= LCUT  <=>  w = -ln(1-u^2) >= 5

// ================= main kernel: 8 outputs (2 float4) per thread =================
__global__ void __launch_bounds__(256) k_main(
    const float*  __restrict__ x,
    const float*  __restrict__ mean,
    const float*  __restrict__ stdv,
    float4*       __restrict__ out,
    unsigned one)
{
    unsigned gtid = blockIdx.x * 256u + threadIdx.x;
    unsigned pos  = gtid * 2u;                 // (b,p) position of first float4
    unsigned p0   = pos % (unsigned)P_PAIRS;   // p0 even, p1 = p0+1 (never wraps: P even)

    float2 xv = *(const float2*)(x + pos);
    float2 mu = __ldg((const float2*)(mean + p0));
    float2 sd = __ldg((const float2*)(stdv + p0));
    float xn0 = __fdividef(xv.x - mu.x, sd.x);
    float xn1 = __fdividef(xv.y - mu.y, sd.y);

    float4 niv4 = *(const float4*)g_negiv;
    ull NIV01 = pk2(niv4.x, niv4.y);
    ull NIV23 = pk2(niv4.z, niv4.w);

    // packed constants (hoisted once per thread)
    const ull NEG1 = pk2(-1.0f, -1.0f);
    const ull TWO  = pk2(2.0f, 2.0f);
    const ull UOFF = pk2(-0.99999994f, -0.99999994f);
    const ull NLN2 = pk2(-0.693147180559945f, -0.693147180559945f);
    const ull M2_5 = pk2(-2.5f, -2.5f);
    const ull ONE2 = pk2(1.0f, 1.0f);
    const ull C8 = pk2( 1.987138e-08f,  1.987138e-08f);
    const ull C7 = pk2( 2.427323e-07f,  2.427323e-07f);
    const ull C6 = pk2(-2.491411e-06f, -2.491411e-06f);
    const ull C5 = pk2(-3.105282e-06f, -3.105282e-06f);
    const ull C4 = pk2( 1.545603e-04f,  1.545603e-04f);
    const ull C3 = pk2(-8.865218e-04f, -8.865218e-04f);
    const ull C2 = pk2(-2.954063e-03f, -2.954063e-03f);
    const ull C1 = pk2( 1.7440262e-01f, 1.7440262e-01f);
    const ull C0 = pk2( 1.0616583f,     1.0616583f);

    unsigned base = pos * 4u;

    #pragma unroll
    for (int g = 0; g < 2; g++) {               // two float4 groups
        unsigned pg = p0 + (unsigned)g;
        float xn = g ? xn1 : xn0;
        ull XN = pk2(xn, xn);
        const float4 a4 = __ldg((const float4*)g_alpha + pg);
        ull A01 = pk2(a4.x, a4.y);
        ull A23 = pk2(a4.z, a4.w);

        unsigned c0 = base + (unsigned)(4 * g);
        unsigned b0 = threefry_bits(c0 + 0u, one);
        unsigned b1 = threefry_bits(c0 + 1u, one);
        unsigned b2 = threefry_bits(c0 + 2u, one);
        unsigned b3 = threefry_bits(c0 + 3u, one);

        ull R[2];
        #pragma unroll
        for (int h = 0; h < 2; h++) {           // two packed pairs per float4
            unsigned ba = h ? b2 : b0;
            unsigned bb = h ? b3 : b1;
            // uniform mapping: g = 1 + m*2^-23 via IMAD (OR == ADD, m < 2^23)
            float ga = __uint_as_float(madd_k<0x3f800000u>(one, ba >> 9));
            float gb = __uint_as_float(madd_k<0x3f800000u>(one, bb >> 9));
            ull G = pk2(ga, gb);
            ull F = add2(G, NEG1);              // g - 1, exact
            ull U = fma2(F, TWO, UOFF);         // u in (-1,1)
            float u0, u1; upk2(u0, u1, U);
            float t0 = fmaf(-u0, u0, 1.0f);     // 1 - u^2
            float t1 = fmaf(-u1, u1, 1.0f);
            float l0 = __log2f(t0);
            float l1 = __log2f(t1);
            ull W = pk2(l0, l1);
            ull S = fma2(W, NLN2, M2_5);        // s = -ln2*l - 2.5
            ull P = fma2(C8, S, C7);
            P = fma2(P, S, C6);
            P = fma2(P, S, C5);
            P = fma2(P, S, C4);
            P = fma2(P, S, C3);
            P = fma2(P, S, C2);
            P = fma2(P, S, C1);
            P = fma2(P, S, C0);
            ull Rp = mul2(U, P);                // 0.5 * normal (coeffs pre-scaled)
            if (l0 <= LCUT || l1 <= LCUT) {     // rare tail (~0.7% of pairs)
                float r0, r1; upk2(r0, r1, Rp);
                if (l0 <= LCUT) r0 = tail_fix(u0, l0);
                if (l1 <= LCUT) r1 = tail_fix(u1, l1);
                Rp = pk2(r0, r1);
            }
            ull A  = h ? A23 : A01;
            ull NI = h ? NIV23 : NIV01;
            ull Q  = fma2(A, NI, ONE2);         // 1 - a/max
            R[h] = fma2(XN, A, mul2(Q, Rp));    // xn*a + q*(0.5*normal)
        }
        float4 o;
        upk2(o.x, o.y, R[0]);
        upk2(o.z, o.w, R[1]);
        out[pos + (unsigned)g] = o;
    }
}

// ================= launch =================
extern "C" void kernel_launch(void* const* d_in, const int* in_sizes, int n_in,
                              void* d_out, int out_size)
{
    const float* x       = (const float*)d_in[0];
    const float* mean    = (const float*)d_in[1];
    const float* stdv    = (const float*)d_in[2];
    const float* weights = (const float*)d_in[3];

    k_setup<<<(P_PAIRS + 255) / 256, 256>>>(weights);
    // total (b,p) positions = 256*123256 = 31,553,536; 2 per thread; /256 = 61628 blocks exact
    k_main<<<(BATCHN * P_PAIRS / 2) / 256, 256>>>(x, mean, stdv, (float4*)d_out, 1u);
    (void)in_sizes; (void)n_in; (void)out_size;
}